// round 7
// baseline (speedup 1.0000x reference)
#include <cuda_runtime.h>
#include <cuda_bf16.h>
#include <cstdint>

// Problem constants (from reference)
#define V_SZ     32000
#define D_SZ     5120
#define T_SZ     32
#define B_SZ     4
#define S_SZ     2048
#define VIS_DIM  768
#define N_SHARED (V_SZ + 2)            // 32002
#define NTOK     (B_SZ * S_SZ)         // 8192
#define NROWS    (B_SZ * T_SZ)         // 128 vision rows

#define THREADS      256
#define ROW_BYTES    (D_SZ * 4)        // 20480 bytes per row
#define NS           6                 // smem pipeline stages
#define LOOKAHEAD    4                 // loads in flight
#define SMEM_BYTES   (128 + NS * ROW_BYTES)   // 123008
#define GRID_GATHER  148
#define TOK_PER_BLK  ((NTOK + GRID_GATHER - 1) / GRID_GATHER)   // 56

#define VCOLS    256                   // cols per vx block
#define VX_GRID  (D_SZ / VCOLS)       // 20
#define RG       8                     // vision rows per register tile

// Scratch: projected vision rows (device global — no allocation)
__device__ __align__(128) float g_vx[(size_t)NROWS * D_SZ];   // 2.6 MB

// ---------------------------------------------------------------------------
// K1: self-scanning vision projection.
// 20 blocks; each block: scan text -> active rows; compute its 256-col chunk
// of vx for active rows, 8 rows per register tile (fc_w loaded once/tile).
// ---------------------------------------------------------------------------
__global__ __launch_bounds__(THREADS)
void vx_kernel(const int4*  __restrict__ text4,   // [NTOK/4]
               const float* __restrict__ vis,     // [B*T, VIS_DIM]
               const float* __restrict__ fc_w,    // [VIS_DIM, D]
               const float* __restrict__ fc_b)    // [D]
{
    __shared__ int   s_used[NROWS];
    __shared__ int   s_rows[NROWS];
    __shared__ int   s_nact;
    __shared__ float s_vis[RG][VIS_DIM];          // 24 KB

    const int tid = threadIdx.x;

    if (tid < NROWS) s_used[tid] = 0;
    __syncthreads();

    // scan all 8192 ids: 8 int4 per thread
    #pragma unroll
    for (int j = 0; j < 8; j++) {
        int  vecidx = tid * 8 + j;                // 0..2047
        int4 v = __ldg(&text4[vecidx]);
        int  ids[4] = { v.x, v.y, v.z, v.w };
        #pragma unroll
        for (int k = 0; k < 4; k++) {
            int id = ids[k];
            if (id >= N_SHARED) {
                int tv = id - N_SHARED; if (tv > T_SZ - 1) tv = T_SZ - 1;
                int tokidx = vecidx * 4 + k;
                int b = tokidx >> 11;             // / S_SZ
                s_used[b * T_SZ + tv] = 1;        // benign race
            }
        }
    }
    __syncthreads();

    if (tid == 0) {
        int n = 0;
        for (int r = 0; r < NROWS; r++)
            if (s_used[r]) s_rows[n++] = r;
        s_nact = n;
    }
    __syncthreads();

    const int nact = s_nact;
    if (nact == 0) return;

    const int   col  = blockIdx.x * VCOLS + tid;
    const float bias = __ldg(&fc_b[col]);

    for (int g = 0; g < nact; g += RG) {
        const int ng = min(RG, nact - g);

        // stage up to 8 vision rows in smem
        for (int r = 0; r < ng; r++) {
            const float* vrow = vis + (size_t)s_rows[g + r] * VIS_DIM;
            for (int i = tid; i < VIS_DIM; i += THREADS)
                s_vis[r][i] = vrow[i];
        }
        __syncthreads();

        float acc[RG];
        #pragma unroll
        for (int r = 0; r < RG; r++) acc[r] = bias;

        const float* w = fc_w + col;
        #pragma unroll 4
        for (int k = 0; k < VIS_DIM; k++) {
            float wv = __ldg(&w[(size_t)k * D_SZ]);
            #pragma unroll
            for (int r = 0; r < RG; r++)
                acc[r] = fmaf(s_vis[r][k], wv, acc[r]);
        }

        for (int r = 0; r < ng; r++)
            g_vx[(size_t)s_rows[g + r] * D_SZ + col] = acc[r];
        __syncthreads();
    }
}

// ---------------------------------------------------------------------------
// K2: TMA bulk-copy gather. Persistent: 148 blocks, ~56 tokens each.
// Thread 0 drives a 6-stage 20KB smem ring:
//   cp.async.bulk G->S (mbarrier complete_tx), then cp.async.bulk S->G.
// ---------------------------------------------------------------------------
__global__ __launch_bounds__(THREADS)
void gather_tma_kernel(const int*   __restrict__ text,
                       const float* __restrict__ weight,
                       const float* __restrict__ fig,
                       float*       __restrict__ out)
{
    extern __shared__ __align__(128) char dsmem[];
    __shared__ int s_ids[TOK_PER_BLK];

    const int t0 = blockIdx.x * TOK_PER_BLK;
    const int n  = min(TOK_PER_BLK, NTOK - t0);
    if (n <= 0) return;

    const int tid = threadIdx.x;

    // cooperative id prefetch into smem
    for (int i = tid; i < n; i += THREADS) s_ids[i] = __ldg(&text[t0 + i]);
    __syncthreads();

    if (tid != 0) return;

    uint32_t smem_base;
    asm("{ .reg .u64 t; cvta.to.shared.u64 t, %1; cvt.u32.u64 %0, t; }"
        : "=r"(smem_base) : "l"(dsmem));
    const uint32_t mbar0 = smem_base;          // 6 x 8B mbarriers
    const uint32_t buf0  = smem_base + 128;    // 6 x 20480B buffers

    #pragma unroll
    for (int s = 0; s < NS; s++)
        asm volatile("mbarrier.init.shared.b64 [%0], 1;"
                     :: "r"(mbar0 + s * 8) : "memory");
    asm volatile("fence.proxy.async.shared::cta;" ::: "memory");

    // source pointer for token local index t
    auto src_of = [&](int t) -> const char* {
        int id = s_ids[t];
        if (id < V_SZ)          return (const char*)(weight + (size_t)id * D_SZ);
        if (id < N_SHARED)      return (const char*)(fig + (size_t)(id - V_SZ) * D_SZ);
        int tv = id - N_SHARED; if (tv > T_SZ - 1) tv = T_SZ - 1;
        int b = (t0 + t) >> 11; // / S_SZ
        return (const char*)(g_vx + ((size_t)(b * T_SZ + tv)) * D_SZ);
    };

    auto issue_load = [&](int t) {
        uint32_t mb  = mbar0 + (t % NS) * 8;
        uint32_t dst = buf0 + (uint32_t)(t % NS) * ROW_BYTES;
        asm volatile("mbarrier.arrive.expect_tx.shared.b64 _, [%0], %1;"
                     :: "r"(mb), "r"((uint32_t)ROW_BYTES) : "memory");
        asm volatile("cp.async.bulk.shared::cta.global.mbarrier::complete_tx::bytes "
                     "[%0], [%1], %2, [%3];"
                     :: "r"(dst), "l"(src_of(t)), "r"((uint32_t)ROW_BYTES), "r"(mb)
                     : "memory");
    };

    // prologue: fill lookahead
    const int npro = n < LOOKAHEAD ? n : LOOKAHEAD;
    for (int t = 0; t < npro; t++) issue_load(t);

    for (int t = 0; t < n; t++) {
        const uint32_t mb     = mbar0 + (t % NS) * 8;
        const uint32_t buf    = buf0 + (uint32_t)(t % NS) * ROW_BYTES;
        const uint32_t parity = (uint32_t)((t / NS) & 1);

        // wait for this stage's load
        {
            uint32_t done;
            asm volatile(
                "{\n\t.reg .pred p;\n\t"
                "mbarrier.try_wait.parity.acquire.cta.shared::cta.b64 p, [%1], %2;\n\t"
                "selp.b32 %0, 1, 0, p;\n\t}"
                : "=r"(done) : "r"(mb), "r"(parity) : "memory");
            if (!done) {
                asm volatile(
                    "{\n\t.reg .pred P1;\n\t"
                    "W_%=:\n\t"
                    "mbarrier.try_wait.parity.acquire.cta.shared::cta.b64 P1, [%0], %1, 0x989680;\n\t"
                    "@P1 bra.uni D_%=;\n\t"
                    "bra.uni W_%=;\n\t"
                    "D_%=:\n\t}"
                    :: "r"(mb), "r"(parity) : "memory");
            }
        }

        // bulk store this token's row
        char* dst = (char*)(out + (size_t)(t0 + t) * D_SZ);
        asm volatile("cp.async.bulk.global.shared::cta.bulk_group [%0], [%1], %2;"
                     :: "l"(dst), "r"(buf), "r"((uint32_t)ROW_BYTES) : "memory");
        asm volatile("cp.async.bulk.commit_group;" ::: "memory");

        // refill: buffer (t+LOOKAHEAD)%NS is free once store (t+LOOKAHEAD-NS)
        // has been read: allow NS-LOOKAHEAD=2 outstanding store groups.
        if (t + LOOKAHEAD < n) {
            asm volatile("cp.async.bulk.wait_group.read 2;" ::: "memory");
            issue_load(t + LOOKAHEAD);
        }
    }

    // drain all stores before exit
    asm volatile("cp.async.bulk.wait_group 0;" ::: "memory");
}

extern "C" void kernel_launch(void* const* d_in, const int* in_sizes, int n_in,
                              void* d_out, int out_size)
{
    const int*   text   = (const int*)  d_in[0];  // [B,S] int32
    const float* vis    = (const float*)d_in[1];  // [B,T,VIS_DIM]
    const float* weight = (const float*)d_in[2];  // [V,D]
    const float* fig    = (const float*)d_in[3];  // [2,D]
    const float* fc_w   = (const float*)d_in[4];  // [VIS_DIM,D]
    const float* fc_b   = (const float*)d_in[5];  // [D]
    float*       out    = (float*)d_out;

    vx_kernel<<<VX_GRID, THREADS>>>((const int4*)text, vis, fc_w, fc_b);

    cudaFuncSetAttribute(gather_tma_kernel,
                         cudaFuncAttributeMaxDynamicSharedMemorySize, SMEM_BYTES);
    gather_tma_kernel<<<GRID_GATHER, THREADS, SMEM_BYTES>>>(text, weight, fig, out);
}

// round 10
// speedup vs baseline: 1.8170x; 1.8170x over previous
#include <cuda_runtime.h>
#include <cuda_bf16.h>
#include <cstdint>

// Problem constants (from reference)
#define V_SZ     32000
#define D_SZ     5120
#define T_SZ     32
#define B_SZ     4
#define S_SZ     2048
#define VIS_DIM  768
#define N_SHARED (V_SZ + 2)            // 32002
#define NTOK     (B_SZ * S_SZ)         // 8192

#define THREADS      256
#define ROW_BYTES    (D_SZ * 4)        // 20480 B per row
#define NS           5                 // smem pipeline stages (gather)
#define LOOKAHEAD    3                 // bulk loads in flight
#define GRID_GATHER  148
#define TOK_PER_BLK  56                // 146*56 >= 8192

// vision role
#define NSLICE       16
#define SLICE        (NTOK / NSLICE)   // 512 tokens per slice
#define NCH          10                // col chunks
#define VCH          (D_SZ / NCH)      // 512 cols per chunk
#define RG           4                 // vision tokens per compute group

#define GRID_TOTAL   (GRID_GATHER + NSLICE * NCH)     // 308

// dynamic smem: mbar(NS*8, pad to 256) + NS ring buffers   -> 102656 B
#define SMEM_BYTES   (256 + NS * ROW_BYTES)

__global__ __launch_bounds__(THREADS)
void embed_kernel(const int*   __restrict__ text,
                  const float* __restrict__ vis,      // [B*T, VIS_DIM]
                  const float* __restrict__ weight,   // [V, D]
                  const float* __restrict__ fig,      // [2, D]
                  const float* __restrict__ fc_w,     // [VIS_DIM, D]
                  const float* __restrict__ fc_b,     // [D]
                  float*       __restrict__ out)      // [B*S, D]
{
    extern __shared__ __align__(128) char dsmem[];
    const int tid = threadIdx.x;

    if (blockIdx.x < GRID_GATHER) {
        // ================= gather role: TMA bulk copy of shared rows =======
        __shared__ int s_ids[TOK_PER_BLK];
        __shared__ int s_list[TOK_PER_BLK];   // compacted local indices
        __shared__ int s_m;

        const int t0 = blockIdx.x * TOK_PER_BLK;
        const int n  = min(TOK_PER_BLK, NTOK - t0);
        if (n <= 0) return;

        for (int i = tid; i < n; i += THREADS) s_ids[i] = __ldg(&text[t0 + i]);
        __syncthreads();

        if (tid != 0) return;

        // compact: shared-vocab tokens only (vision handled by other role)
        int m = 0;
        for (int i = 0; i < n; i++)
            if (s_ids[i] < N_SHARED) s_list[m++] = i;
        s_m = m;
        if (m == 0) return;

        uint32_t smem_base;
        asm("{ .reg .u64 t; cvta.to.shared.u64 t, %1; cvt.u32.u64 %0, t; }"
            : "=r"(smem_base) : "l"(dsmem));
        const uint32_t mbar0 = smem_base;
        const uint32_t buf0  = smem_base + 256;

        #pragma unroll
        for (int s = 0; s < NS; s++)
            asm volatile("mbarrier.init.shared.b64 [%0], 1;"
                         :: "r"(mbar0 + s * 8) : "memory");
        asm volatile("fence.proxy.async.shared::cta;" ::: "memory");

        auto src_of = [&](int j) -> const char* {
            int id = s_ids[s_list[j]];
            if (id < V_SZ) return (const char*)(weight + (size_t)id * D_SZ);
            return (const char*)(fig + (size_t)(id - V_SZ) * D_SZ);
        };

        auto issue_load = [&](int j) {
            uint32_t mb  = mbar0 + (j % NS) * 8;
            uint32_t dst = buf0 + (uint32_t)(j % NS) * ROW_BYTES;
            asm volatile("mbarrier.arrive.expect_tx.shared.b64 _, [%0], %1;"
                         :: "r"(mb), "r"((uint32_t)ROW_BYTES) : "memory");
            asm volatile("cp.async.bulk.shared::cta.global.mbarrier::complete_tx::bytes "
                         "[%0], [%1], %2, [%3];"
                         :: "r"(dst), "l"(src_of(j)), "r"((uint32_t)ROW_BYTES), "r"(mb)
                         : "memory");
        };

        const int npro = m < LOOKAHEAD ? m : LOOKAHEAD;
        for (int j = 0; j < npro; j++) issue_load(j);

        for (int j = 0; j < m; j++) {
            const uint32_t mb     = mbar0 + (j % NS) * 8;
            const uint32_t buf    = buf0 + (uint32_t)(j % NS) * ROW_BYTES;
            const uint32_t parity = (uint32_t)((j / NS) & 1);

            uint32_t done;
            asm volatile(
                "{\n\t.reg .pred p;\n\t"
                "mbarrier.try_wait.parity.acquire.cta.shared::cta.b64 p, [%1], %2;\n\t"
                "selp.b32 %0, 1, 0, p;\n\t}"
                : "=r"(done) : "r"(mb), "r"(parity) : "memory");
            if (!done) {
                asm volatile(
                    "{\n\t.reg .pred P1;\n\t"
                    "W_%=:\n\t"
                    "mbarrier.try_wait.parity.acquire.cta.shared::cta.b64 P1, [%0], %1, 0x989680;\n\t"
                    "@P1 bra.uni D_%=;\n\t"
                    "bra.uni W_%=;\n\t"
                    "D_%=:\n\t}"
                    :: "r"(mb), "r"(parity) : "memory");
            }

            char* dst = (char*)(out + (size_t)(t0 + s_list[j]) * D_SZ);
            asm volatile("cp.async.bulk.global.shared::cta.bulk_group [%0], [%1], %2;"
                         :: "l"(dst), "r"(buf), "r"((uint32_t)ROW_BYTES) : "memory");
            asm volatile("cp.async.bulk.commit_group;" ::: "memory");

            if (j + LOOKAHEAD < m) {
                // stage (j+LOOKAHEAD)%NS reusable once store j+LOOKAHEAD-NS read
                asm volatile("cp.async.bulk.wait_group.read 2;" ::: "memory");
                issue_load(j + LOOKAHEAD);
            }
        }
        asm volatile("cp.async.bulk.wait_group 0;" ::: "memory");
    } else {
        // ================= vision role: project directly into out ==========
        const int role  = blockIdx.x - GRID_GATHER;
        const int slice = role / NCH;
        const int chunk = role % NCH;
        const int base  = slice * SLICE;

        __shared__ int s_cnt;
        // carve dynamic smem: token list + staged vis rows
        int*   s_list = (int*)dsmem;                         // [SLICE]
        float (*s_vis)[VIS_DIM] = (float (*)[VIS_DIM])(dsmem + SLICE * 4);

        if (tid == 0) s_cnt = 0;
        __syncthreads();

        // scan this slice's 512 ids
        #pragma unroll
        for (int j = 0; j < SLICE / THREADS; j++) {
            int i  = tid + j * THREADS;
            int id = __ldg(&text[base + i]);
            if (id >= N_SHARED) {
                int slot = atomicAdd(&s_cnt, 1);
                s_list[slot] = i;
            }
        }
        __syncthreads();

        const int cnt = s_cnt;
        if (cnt == 0) return;

        const int    col  = chunk * VCH + tid * 2;
        const float2 bias = *(const float2*)(fc_b + col);

        for (int g = 0; g < cnt; g += RG) {
            const int ng = min(RG, cnt - g);

            // stage up to RG vision rows
            for (int r = 0; r < ng; r++) {
                int tok = base + s_list[g + r];
                int id  = __ldg(&text[tok]);
                int tv  = id - N_SHARED; if (tv > T_SZ - 1) tv = T_SZ - 1;
                int b   = tok >> 11;                     // / S_SZ
                const float* vrow = vis + ((size_t)(b * T_SZ + tv)) * VIS_DIM;
                for (int i = tid; i < VIS_DIM; i += THREADS)
                    s_vis[r][i] = vrow[i];
            }
            __syncthreads();

            float2 acc[RG];
            #pragma unroll
            for (int r = 0; r < RG; r++) acc[r] = bias;

            const float2* w2 = (const float2*)(fc_w + col);
            #pragma unroll 8
            for (int k = 0; k < VIS_DIM; k++) {
                float2 w = __ldg(&w2[(size_t)k * (D_SZ / 2)]);
                #pragma unroll
                for (int r = 0; r < RG; r++) {
                    float a = s_vis[r][k];
                    acc[r].x = fmaf(a, w.x, acc[r].x);
                    acc[r].y = fmaf(a, w.y, acc[r].y);
                }
            }

            for (int r = 0; r < ng; r++) {
                int tok = base + s_list[g + r];
                *(float2*)(out + (size_t)tok * D_SZ + col) = acc[r];
            }
            __syncthreads();   // before s_vis reuse
        }
    }
}

extern "C" void kernel_launch(void* const* d_in, const int* in_sizes, int n_in,
                              void* d_out, int out_size)
{
    const int*   text   = (const int*)  d_in[0];  // [B,S] int32
    const float* vis    = (const float*)d_in[1];  // [B,T,VIS_DIM]
    const float* weight = (const float*)d_in[2];  // [V,D]
    const float* fig    = (const float*)d_in[3];  // [2,D]
    const float* fc_w   = (const float*)d_in[4];  // [VIS_DIM,D]
    const float* fc_b   = (const float*)d_in[5];  // [D]
    float*       out    = (float*)d_out;

    cudaFuncSetAttribute(embed_kernel,
                         cudaFuncAttributeMaxDynamicSharedMemorySize, SMEM_BYTES);
    embed_kernel<<<GRID_TOTAL, THREADS, SMEM_BYTES>>>(text, vis, weight, fig,
                                                      fc_w, fc_b, out);
}

// round 12
// speedup vs baseline: 2.6074x; 1.4350x over previous
#include <cuda_runtime.h>
#include <cuda_bf16.h>
#include <cstdint>

// Problem constants (from reference)
#define V_SZ     32000
#define D_SZ     5120
#define T_SZ     32
#define B_SZ     4
#define S_SZ     2048
#define VIS_DIM  768
#define N_SHARED (V_SZ + 2)            // 32002
#define NTOK     (B_SZ * S_SZ)         // 8192

// ---------------- K2 gather (TMA ring) — exact R7 config ----------------
#define THREADS      256
#define ROW_BYTES    (D_SZ * 4)        // 20480 B per row
#define NS           6
#define LOOKAHEAD    4
#define SMEM_BYTES   (128 + NS * ROW_BYTES)   // 123008
#define GRID_GATHER  148
#define TOK_PER_BLK  56                // 147*56 >= 8192

// ---------------- K1 vision -------------------------------------------
#define NSLICE       16
#define SLICE        (NTOK / NSLICE)   // 512
#define VCOLS        64                // cols per block
#define NCH          (D_SZ / VCOLS)    // 80
#define KSPLIT       4
#define KSEG         (VIS_DIM / KSPLIT) // 192

// ---------------------------------------------------------------------------
// K1: vision projection directly into out. 1280 blocks; most exit instantly.
// Active: 1 token at a time, 4-way k-split, 8-wide load/FMA batches.
// ---------------------------------------------------------------------------
__global__ __launch_bounds__(THREADS)
void vision_kernel(const int*   __restrict__ text,
                   const float* __restrict__ vis,     // [B*T, VIS_DIM]
                   const float* __restrict__ fc_w,    // [VIS_DIM, D]
                   const float* __restrict__ fc_b,    // [D]
                   float*       __restrict__ out)     // [B*S, D]
{
    const int slice = blockIdx.x / NCH;
    const int chunk = blockIdx.x % NCH;
    const int base  = slice * SLICE;
    const int tid   = threadIdx.x;

    __shared__ int   s_cnt;
    __shared__ int   s_list[SLICE > 64 ? 64 : SLICE];   // vision tokens in slice
    __shared__ float s_vis[VIS_DIM];
    __shared__ float s_part[KSPLIT][VCOLS];

    if (tid == 0) s_cnt = 0;
    __syncthreads();

    // scan this slice's 512 ids (int4 vectorized: 128 int4, threads 0..127)
    if (tid < SLICE / 4) {
        int4 v = __ldg((const int4*)(text + base) + tid);
        int ids[4] = { v.x, v.y, v.z, v.w };
        #pragma unroll
        for (int k = 0; k < 4; k++)
            if (ids[k] >= N_SHARED) {
                int slot = atomicAdd(&s_cnt, 1);
                if (slot < 64) s_list[slot] = tid * 4 + k;
            }
    }
    __syncthreads();

    const int cnt = s_cnt < 64 ? s_cnt : 64;
    if (cnt == 0) return;

    const int kseg = tid >> 6;               // 0..3
    const int ci   = tid & 63;               // 0..63
    const int col  = chunk * VCOLS + ci;

    for (int g = 0; g < cnt; g++) {
        const int tok = base + s_list[g];
        int id = __ldg(&text[tok]);
        int tv = id - N_SHARED; if (tv > T_SZ - 1) tv = T_SZ - 1;
        int b  = tok >> 11;                  // / S_SZ
        const float* vrow = vis + ((size_t)(b * T_SZ + tv)) * VIS_DIM;
        for (int i = tid; i < VIS_DIM; i += THREADS) s_vis[i] = vrow[i];
        __syncthreads();

        // 192 MACs for this k-segment: 24 explicit 8-wide batches
        const float* w = fc_w + col;
        float acc = 0.f;
        const int k0 = kseg * KSEG;
        #pragma unroll 4
        for (int kb = 0; kb < KSEG; kb += 8) {
            float wr[8];
            #pragma unroll
            for (int u = 0; u < 8; u++)
                wr[u] = __ldg(&w[(size_t)(k0 + kb + u) * D_SZ]);
            #pragma unroll
            for (int u = 0; u < 8; u++)
                acc = fmaf(s_vis[k0 + kb + u], wr[u], acc);
        }

        s_part[kseg][ci] = acc;
        __syncthreads();

        if (tid < VCOLS) {
            float r = s_part[0][tid] + s_part[1][tid]
                    + s_part[2][tid] + s_part[3][tid]
                    + __ldg(&fc_b[chunk * VCOLS + tid]);
            out[(size_t)tok * D_SZ + chunk * VCOLS + tid] = r;
        }
        __syncthreads();   // before s_vis/s_part reuse
    }
}

// ---------------------------------------------------------------------------
// K2: TMA bulk-copy gather of shared-vocab rows (skips vision tokens).
// Exact R7 pipeline: 148 blocks, 6-stage 20KB ring, lookahead 4.
// ---------------------------------------------------------------------------
__global__ __launch_bounds__(THREADS)
void gather_tma_kernel(const int*   __restrict__ text,
                       const float* __restrict__ weight,
                       const float* __restrict__ fig,
                       float*       __restrict__ out)
{
    extern __shared__ __align__(128) char dsmem[];
    __shared__ int s_ids[TOK_PER_BLK];
    __shared__ int s_list[TOK_PER_BLK];

    const int t0 = blockIdx.x * TOK_PER_BLK;
    const int n  = min(TOK_PER_BLK, NTOK - t0);
    if (n <= 0) return;

    const int tid = threadIdx.x;
    for (int i = tid; i < n; i += THREADS) s_ids[i] = __ldg(&text[t0 + i]);
    __syncthreads();

    if (tid != 0) return;

    // compact to shared-vocab tokens (vision rows written by K1)
    int m = 0;
    for (int i = 0; i < n; i++)
        if (s_ids[i] < N_SHARED) s_list[m++] = i;
    if (m == 0) return;

    uint32_t smem_base;
    asm("{ .reg .u64 t; cvta.to.shared.u64 t, %1; cvt.u32.u64 %0, t; }"
        : "=r"(smem_base) : "l"(dsmem));
    const uint32_t mbar0 = smem_base;
    const uint32_t buf0  = smem_base + 128;

    #pragma unroll
    for (int s = 0; s < NS; s++)
        asm volatile("mbarrier.init.shared.b64 [%0], 1;"
                     :: "r"(mbar0 + s * 8) : "memory");
    asm volatile("fence.proxy.async.shared::cta;" ::: "memory");

    auto src_of = [&](int j) -> const char* {
        int id = s_ids[s_list[j]];
        if (id < V_SZ) return (const char*)(weight + (size_t)id * D_SZ);
        return (const char*)(fig + (size_t)(id - V_SZ) * D_SZ);
    };

    auto issue_load = [&](int j) {
        uint32_t mb  = mbar0 + (j % NS) * 8;
        uint32_t dst = buf0 + (uint32_t)(j % NS) * ROW_BYTES;
        asm volatile("mbarrier.arrive.expect_tx.shared.b64 _, [%0], %1;"
                     :: "r"(mb), "r"((uint32_t)ROW_BYTES) : "memory");
        asm volatile("cp.async.bulk.shared::cta.global.mbarrier::complete_tx::bytes "
                     "[%0], [%1], %2, [%3];"
                     :: "r"(dst), "l"(src_of(j)), "r"((uint32_t)ROW_BYTES), "r"(mb)
                     : "memory");
    };

    const int npro = m < LOOKAHEAD ? m : LOOKAHEAD;
    for (int j = 0; j < npro; j++) issue_load(j);

    for (int j = 0; j < m; j++) {
        const uint32_t mb     = mbar0 + (j % NS) * 8;
        const uint32_t buf    = buf0 + (uint32_t)(j % NS) * ROW_BYTES;
        const uint32_t parity = (uint32_t)((j / NS) & 1);

        uint32_t done;
        asm volatile(
            "{\n\t.reg .pred p;\n\t"
            "mbarrier.try_wait.parity.acquire.cta.shared::cta.b64 p, [%1], %2;\n\t"
            "selp.b32 %0, 1, 0, p;\n\t}"
            : "=r"(done) : "r"(mb), "r"(parity) : "memory");
        if (!done) {
            asm volatile(
                "{\n\t.reg .pred P1;\n\t"
                "W_%=:\n\t"
                "mbarrier.try_wait.parity.acquire.cta.shared::cta.b64 P1, [%0], %1, 0x989680;\n\t"
                "@P1 bra.uni D_%=;\n\t"
                "bra.uni W_%=;\n\t"
                "D_%=:\n\t}"
                :: "r"(mb), "r"(parity) : "memory");
        }

        char* dst = (char*)(out + (size_t)(t0 + s_list[j]) * D_SZ);
        asm volatile("cp.async.bulk.global.shared::cta.bulk_group [%0], [%1], %2;"
                     :: "l"(dst), "r"(buf), "r"((uint32_t)ROW_BYTES) : "memory");
        asm volatile("cp.async.bulk.commit_group;" ::: "memory");

        if (j + LOOKAHEAD < m) {
            asm volatile("cp.async.bulk.wait_group.read 2;" ::: "memory");
            issue_load(j + LOOKAHEAD);
        }
    }
    asm volatile("cp.async.bulk.wait_group 0;" ::: "memory");
}

extern "C" void kernel_launch(void* const* d_in, const int* in_sizes, int n_in,
                              void* d_out, int out_size)
{
    const int*   text   = (const int*)  d_in[0];  // [B,S] int32
    const float* vis    = (const float*)d_in[1];  // [B,T,VIS_DIM]
    const float* weight = (const float*)d_in[2];  // [V,D]
    const float* fig    = (const float*)d_in[3];  // [2,D]
    const float* fc_w   = (const float*)d_in[4];  // [VIS_DIM,D]
    const float* fc_b   = (const float*)d_in[5];  // [D]
    float*       out    = (float*)d_out;

    vision_kernel<<<NSLICE * NCH, THREADS>>>(text, vis, fc_w, fc_b, out);

    cudaFuncSetAttribute(gather_tma_kernel,
                         cudaFuncAttributeMaxDynamicSharedMemorySize, SMEM_BYTES);
    gather_tma_kernel<<<GRID_GATHER, THREADS, SMEM_BYTES>>>(text, weight, fig, out);
}

// round 13
// speedup vs baseline: 3.0946x; 1.1869x over previous
#include <cuda_runtime.h>
#include <cuda_bf16.h>
#include <cstdint>

// Problem constants (from reference)
#define V_SZ     32000
#define D_SZ     5120
#define T_SZ     32
#define B_SZ     4
#define S_SZ     2048
#define VIS_DIM  768
#define N_SHARED (V_SZ + 2)            // 32002
#define NTOK     (B_SZ * S_SZ)         // 8192

// ---------------- K2 gather (TMA ring) — proven config ----------------
#define THREADS      256
#define ROW_BYTES    (D_SZ * 4)        // 20480 B per row
#define NS           6
#define LOOKAHEAD    4
#define SMEM_BYTES   (128 + NS * ROW_BYTES)   // 123008
#define GRID_GATHER  148
#define TOK_PER_BLK  56                // 147*56 >= 8192

// ---------------- K1 vision ------------------------------------------
#define NSLICE       32
#define SLICE        (NTOK / NSLICE)   // 256 tokens per slice
#define VCOLS        32                // cols per block
#define NCH          (D_SZ / VCOLS)    // 160
#define KSPLIT       8
#define KSEG         (VIS_DIM / KSPLIT) // 96
#define MAXLIST      32

// ---------------------------------------------------------------------------
// K1: vision projection directly into out. 5120 tiny blocks; nearly all exit
// after scanning 256 ids. Active: 32 cols x 8 k-segments, 12 batches of 8.
// ---------------------------------------------------------------------------
__global__ __launch_bounds__(THREADS)
void vision_kernel(const int*   __restrict__ text,
                   const float* __restrict__ vis,     // [B*T, VIS_DIM]
                   const float* __restrict__ fc_w,    // [VIS_DIM, D]
                   const float* __restrict__ fc_b,    // [D]
                   float*       __restrict__ out)     // [B*S, D]
{
    const int slice = blockIdx.x / NCH;
    const int chunk = blockIdx.x % NCH;
    const int base  = slice * SLICE;
    const int tid   = threadIdx.x;

    __shared__ int   s_cnt;
    __shared__ int   s_list[MAXLIST];
    __shared__ float s_vis[VIS_DIM];
    __shared__ float s_part[KSPLIT][VCOLS];

    if (tid == 0) s_cnt = 0;
    __syncthreads();

    // scan 256 ids: 64 int4, threads 0..63
    if (tid < SLICE / 4) {
        int4 v = __ldg((const int4*)(text + base) + tid);
        int ids[4] = { v.x, v.y, v.z, v.w };
        #pragma unroll
        for (int k = 0; k < 4; k++)
            if (ids[k] >= N_SHARED) {
                int slot = atomicAdd(&s_cnt, 1);
                if (slot < MAXLIST) s_list[slot] = tid * 4 + k;
            }
    }
    __syncthreads();

    const int cnt = s_cnt < MAXLIST ? s_cnt : MAXLIST;
    if (cnt == 0) return;

    const int kseg = tid >> 5;               // 0..7
    const int ci   = tid & 31;               // 0..31
    const int col  = chunk * VCOLS + ci;
    const int k0   = kseg * KSEG;

    for (int g = 0; g < cnt; g++) {
        const int tok = base + s_list[g];
        int id = __ldg(&text[tok]);
        int tv = id - N_SHARED; if (tv > T_SZ - 1) tv = T_SZ - 1;
        int b  = tok >> 11;                  // / S_SZ
        const float* vrow = vis + ((size_t)(b * T_SZ + tv)) * VIS_DIM;
        for (int i = tid; i < VIS_DIM; i += THREADS) s_vis[i] = vrow[i];
        __syncthreads();

        // 96 MACs: 12 batches of 8 wide loads (warp -> 1 line per load)
        const float* w = fc_w + col;
        float acc = 0.f;
        #pragma unroll
        for (int kb = 0; kb < KSEG; kb += 8) {
            float wr[8];
            #pragma unroll
            for (int u = 0; u < 8; u++)
                wr[u] = __ldg(&w[(size_t)(k0 + kb + u) * D_SZ]);
            #pragma unroll
            for (int u = 0; u < 8; u++)
                acc = fmaf(s_vis[k0 + kb + u], wr[u], acc);
        }

        s_part[kseg][ci] = acc;
        __syncthreads();

        if (tid < VCOLS) {
            float r = __ldg(&fc_b[chunk * VCOLS + tid]);
            #pragma unroll
            for (int p = 0; p < KSPLIT; p++) r += s_part[p][tid];
            out[(size_t)tok * D_SZ + chunk * VCOLS + tid] = r;
        }
        __syncthreads();   // before s_vis/s_part reuse
    }
}

// ---------------------------------------------------------------------------
// K2: TMA bulk-copy gather of shared-vocab rows (skips vision tokens).
// 148 blocks, 6-stage 20KB smem ring, lookahead 4.
// ---------------------------------------------------------------------------
__global__ __launch_bounds__(THREADS)
void gather_tma_kernel(const int*   __restrict__ text,
                       const float* __restrict__ weight,
                       const float* __restrict__ fig,
                       float*       __restrict__ out)
{
    extern __shared__ __align__(128) char dsmem[];
    __shared__ int s_ids[TOK_PER_BLK];
    __shared__ int s_list[TOK_PER_BLK];

    const int t0 = blockIdx.x * TOK_PER_BLK;
    const int n  = min(TOK_PER_BLK, NTOK - t0);
    if (n <= 0) return;

    const int tid = threadIdx.x;
    for (int i = tid; i < n; i += THREADS) s_ids[i] = __ldg(&text[t0 + i]);
    __syncthreads();

    if (tid != 0) return;

    int m = 0;
    for (int i = 0; i < n; i++)
        if (s_ids[i] < N_SHARED) s_list[m++] = i;
    if (m == 0) return;

    uint32_t smem_base;
    asm("{ .reg .u64 t; cvta.to.shared.u64 t, %1; cvt.u32.u64 %0, t; }"
        : "=r"(smem_base) : "l"(dsmem));
    const uint32_t mbar0 = smem_base;
    const uint32_t buf0  = smem_base + 128;

    #pragma unroll
    for (int s = 0; s < NS; s++)
        asm volatile("mbarrier.init.shared.b64 [%0], 1;"
                     :: "r"(mbar0 + s * 8) : "memory");
    asm volatile("fence.proxy.async.shared::cta;" ::: "memory");

    auto src_of = [&](int j) -> const char* {
        int id = s_ids[s_list[j]];
        if (id < V_SZ) return (const char*)(weight + (size_t)id * D_SZ);
        return (const char*)(fig + (size_t)(id - V_SZ) * D_SZ);
    };

    auto issue_load = [&](int j) {
        uint32_t mb  = mbar0 + (j % NS) * 8;
        uint32_t dst = buf0 + (uint32_t)(j % NS) * ROW_BYTES;
        asm volatile("mbarrier.arrive.expect_tx.shared.b64 _, [%0], %1;"
                     :: "r"(mb), "r"((uint32_t)ROW_BYTES) : "memory");
        asm volatile("cp.async.bulk.shared::cta.global.mbarrier::complete_tx::bytes "
                     "[%0], [%1], %2, [%3];"
                     :: "r"(dst), "l"(src_of(j)), "r"((uint32_t)ROW_BYTES), "r"(mb)
                     : "memory");
    };

    const int npro = m < LOOKAHEAD ? m : LOOKAHEAD;
    for (int j = 0; j < npro; j++) issue_load(j);

    for (int j = 0; j < m; j++) {
        const uint32_t mb     = mbar0 + (j % NS) * 8;
        const uint32_t buf    = buf0 + (uint32_t)(j % NS) * ROW_BYTES;
        const uint32_t parity = (uint32_t)((j / NS) & 1);

        uint32_t done;
        asm volatile(
            "{\n\t.reg .pred p;\n\t"
            "mbarrier.try_wait.parity.acquire.cta.shared::cta.b64 p, [%1], %2;\n\t"
            "selp.b32 %0, 1, 0, p;\n\t}"
            : "=r"(done) : "r"(mb), "r"(parity) : "memory");
        if (!done) {
            asm volatile(
                "{\n\t.reg .pred P1;\n\t"
                "W_%=:\n\t"
                "mbarrier.try_wait.parity.acquire.cta.shared::cta.b64 P1, [%0], %1, 0x989680;\n\t"
                "@P1 bra.uni D_%=;\n\t"
                "bra.uni W_%=;\n\t"
                "D_%=:\n\t}"
                :: "r"(mb), "r"(parity) : "memory");
        }

        char* dst = (char*)(out + (size_t)(t0 + s_list[j]) * D_SZ);
        asm volatile("cp.async.bulk.global.shared::cta.bulk_group [%0], [%1], %2;"
                     :: "l"(dst), "r"(buf), "r"((uint32_t)ROW_BYTES) : "memory");
        asm volatile("cp.async.bulk.commit_group;" ::: "memory");

        if (j + LOOKAHEAD < m) {
            asm volatile("cp.async.bulk.wait_group.read 2;" ::: "memory");
            issue_load(j + LOOKAHEAD);
        }
    }
    asm volatile("cp.async.bulk.wait_group 0;" ::: "memory");
}

extern "C" void kernel_launch(void* const* d_in, const int* in_sizes, int n_in,
                              void* d_out, int out_size)
{
    const int*   text   = (const int*)  d_in[0];  // [B,S] int32
    const float* vis    = (const float*)d_in[1];  // [B,T,VIS_DIM]
    const float* weight = (const float*)d_in[2];  // [V,D]
    const float* fig    = (const float*)d_in[3];  // [2,D]
    const float* fc_w   = (const float*)d_in[4];  // [VIS_DIM,D]
    const float* fc_b   = (const float*)d_in[5];  // [D]
    float*       out    = (float*)d_out;

    vision_kernel<<<NSLICE * NCH, THREADS>>>(text, vis, fc_w, fc_b, out);

    cudaFuncSetAttribute(gather_tma_kernel,
                         cudaFuncAttributeMaxDynamicSharedMemorySize, SMEM_BYTES);
    gather_tma_kernel<<<GRID_GATHER, THREADS, SMEM_BYTES>>>(text, weight, fig, out);
}